// round 3
// baseline (speedup 1.0000x reference)
#include <cuda_runtime.h>
#include <math.h>

#define NB      32
#define SAMPLES 5000
#define HW      (512 * 1024)
#define TOTAL   (NB * SAMPLES)
#define SIGMA   0.03f
#define EPS     1e-6f

#define THREADS 256
#define BLOCKS  ((TOTAL + THREADS - 1) / THREADS)   // 625

// zero-initialized at module load; reset by last block every call (graph-safe)
__device__ float        g_acc[3];   // [0]=equal, [1]=unequal, [2]=valid
__device__ unsigned int g_count;

__global__ void __launch_bounds__(THREADS) rl_fused_kernel(
    const float* __restrict__ pred,
    const float* __restrict__ targ,
    const int*   __restrict__ mask,   // bool upcast to int32 by harness
    const int*   __restrict__ idxA,
    const int*   __restrict__ idxB,
    float*       __restrict__ out)
{
    int i = blockIdx.x * blockDim.x + threadIdx.x;

    float eq = 0.0f, uneq = 0.0f, valid = 0.0f;

    if (i < TOTAL) {
        int n = i / SAMPLES;
        long long base = (long long)n * (long long)HW;
        long long ia = base + (long long)idxA[i];
        long long ib = base + (long long)idxB[i];

        // issue all 6 gathers unconditionally -> single DRAM round-trip depth
        int   mA = mask[ia];
        int   mB = mask[ib];
        float tA = targ[ia];
        float tB = targ[ib];
        float pA = pred[ia];
        float pB = pred[ib];

        bool cmask = (mA != 0) && (mB != 0);

        float ratio = tA / (tB + EPS);
        const float hi = 1.0f + SIGMA;
        const float lo = 1.0f / (1.0f + SIGMA);
        bool mask_eq = (ratio < hi) && (ratio > lo);

        float d = pA - pB;
        float eq_val = d * d;

        float label = (ratio >= hi) ? 1.0f : -1.0f;
        float x = (pB - pA) * label;
        float sp = (x > 20.0f) ? x : log1pf(expf(x));

        valid = cmask ? 1.0f : 0.0f;
        eq    = (cmask && mask_eq)  ? eq_val : 0.0f;
        uneq  = (cmask && !mask_eq) ? sp     : 0.0f;
    }

    // --- block reduction ---
    #pragma unroll
    for (int off = 16; off > 0; off >>= 1) {
        eq    += __shfl_down_sync(0xffffffffu, eq,    off);
        uneq  += __shfl_down_sync(0xffffffffu, uneq,  off);
        valid += __shfl_down_sync(0xffffffffu, valid, off);
    }

    __shared__ float s_eq[8], s_uneq[8], s_valid[8];
    __shared__ bool  s_last;
    int lane = threadIdx.x & 31;
    int wid  = threadIdx.x >> 5;
    if (lane == 0) {
        s_eq[wid]    = eq;
        s_uneq[wid]  = uneq;
        s_valid[wid] = valid;
    }
    __syncthreads();

    if (wid == 0) {
        eq    = (lane < (THREADS / 32)) ? s_eq[lane]    : 0.0f;
        uneq  = (lane < (THREADS / 32)) ? s_uneq[lane]  : 0.0f;
        valid = (lane < (THREADS / 32)) ? s_valid[lane] : 0.0f;
        #pragma unroll
        for (int off = 4; off > 0; off >>= 1) {
            eq    += __shfl_down_sync(0xffffffffu, eq,    off);
            uneq  += __shfl_down_sync(0xffffffffu, uneq,  off);
            valid += __shfl_down_sync(0xffffffffu, valid, off);
        }
        if (lane == 0) {
            atomicAdd(&g_acc[0], eq);
            atomicAdd(&g_acc[1], uneq);
            atomicAdd(&g_acc[2], valid);
            __threadfence();
            unsigned ticket = atomicAdd(&g_count, 1u);
            s_last = (ticket == (unsigned)(gridDim.x - 1));
        }
    }
    __syncthreads();

    // last block finalizes and resets state for the next graph replay
    if (s_last && threadIdx.x == 0) {
        float e = g_acc[0], u = g_acc[1], v = g_acc[2];
        out[0] = (e + u) / (v + EPS);   // ALPHA = LOSS_WEIGHT = 1
        g_acc[0] = 0.0f;
        g_acc[1] = 0.0f;
        g_acc[2] = 0.0f;
        __threadfence();
        g_count = 0u;
    }
}

extern "C" void kernel_launch(void* const* d_in, const int* in_sizes, int n_in,
                              void* d_out, int out_size)
{
    const float* pred = (const float*)d_in[0];
    const float* targ = (const float*)d_in[1];
    const int*   mask = (const int*)d_in[2];
    const int*   idxA = (const int*)d_in[3];
    const int*   idxB = (const int*)d_in[4];
    float* out = (float*)d_out;

    rl_fused_kernel<<<BLOCKS, THREADS>>>(pred, targ, mask, idxA, idxB, out);
}